// round 1
// baseline (speedup 1.0000x reference)
#include <cuda_runtime.h>

#define Bb 4
#define Cc 64
#define Hh 256
#define Ww 256
#define Nn (Hh*Ww)
#define NPAIRS 12
#define HALF_S 512
#define MAXS 1024

__device__ unsigned char g_pred[Bb*Nn];
__device__ unsigned char g_pd[Bb*Nn];
__device__ int g_idx[NPAIRS*MAXS];

// argmax over the 4 class planes (softmax preserves argmax)
__global__ void k_argmax(const float* __restrict__ preds) {
    int t = blockIdx.x * blockDim.x + threadIdx.x;
    if (t >= Bb*Nn) return;
    int b = t / Nn, p = t % Nn;
    const float* base = preds + (size_t)b * 4 * Nn + p;
    float best = base[0]; int bi = 0;
#pragma unroll
    for (int c = 1; c < 4; c++) {
        float v = base[(size_t)c * Nn];
        if (v > best) { best = v; bi = c; }
    }
    g_pred[t] = (unsigned char)bi;
}

// 3x3 max-pool, SAME padding (-inf outside -> max over valid neighbors)
__global__ void k_dilate() {
    int t = blockIdx.x * blockDim.x + threadIdx.x;
    if (t >= Bb*Nn) return;
    int b = t / Nn, p = t % Nn;
    int y = p / Ww, x = p % Ww;
    int m = 0;
#pragma unroll
    for (int dy = -1; dy <= 1; dy++) {
        int yy = y + dy;
        if (yy < 0 || yy >= Hh) continue;
#pragma unroll
        for (int dx = -1; dx <= 1; dx++) {
            int xx = x + dx;
            if (xx < 0 || xx >= Ww) continue;
            int v = g_pred[b*Nn + yy*Ww + xx];
            if (v > m) m = v;
        }
    }
    g_pd[t] = (unsigned char)m;
}

// One block per (b, cls) pair. Stable raster-order compaction:
//   hard rank r -> slot r (r < 1024)
//   easy rank e -> slot 512 + max(totH-512, 0) + e (slot < 1024)
__global__ void k_select(const int* __restrict__ labels) {
    int pair = blockIdx.x;
    int b = pair / 3;
    int cls = pair % 3 + 1;
    int tid = threadIdx.x;
    g_idx[pair*MAXS + tid] = -1;   // init this pair's slots

    const int* lab = labels + b*Nn;
    const unsigned char* pd = g_pd + b*Nn;
    int base = tid * 64;

    int cH = 0, cE = 0;
#pragma unroll 4
    for (int i = 0; i < 64; i++) {
        int p = base + i;
        if (lab[p] == cls) { if ((int)pd[p] == cls) cE++; else cH++; }
    }

    // block-wide inclusive scan of packed (hard<<32 | easy)
    unsigned long long v = ((unsigned long long)cH << 32) | (unsigned)cE;
    unsigned long long own = v;
    int lane = tid & 31, wid = tid >> 5;
#pragma unroll
    for (int o = 1; o < 32; o <<= 1) {
        unsigned long long n = __shfl_up_sync(0xffffffffu, v, o);
        if (lane >= o) v += n;
    }
    __shared__ unsigned long long wsum[32];
    __shared__ unsigned long long s_total;
    if (lane == 31) wsum[wid] = v;
    __syncthreads();
    if (wid == 0) {
        unsigned long long w = wsum[lane];
#pragma unroll
        for (int o = 1; o < 32; o <<= 1) {
            unsigned long long n = __shfl_up_sync(0xffffffffu, w, o);
            if (lane >= o) w += n;
        }
        wsum[lane] = w;
        if (lane == 31) s_total = w;
    }
    __syncthreads();

    unsigned long long excl = v - own + (wid > 0 ? wsum[wid-1] : 0ULL);
    int hr = (int)(excl >> 32);
    int er = (int)(excl & 0xffffffffULL);
    int totH = (int)(s_total >> 32);
    int excess = totH > HALF_S ? totH - HALF_S : 0;

    for (int i = 0; i < 64; i++) {
        int p = base + i;
        if (lab[p] == cls) {
            if ((int)pd[p] != cls) {
                if (hr < MAXS) g_idx[pair*MAXS + hr] = p;
                hr++;
            } else {
                int slot = HALF_S + excess + er;
                if (slot < MAXS) g_idx[pair*MAXS + slot] = p;
                er++;
            }
        }
    }
}

// out[pair][c][s] = idx>=0 ? feat[b][c][idx] : 0 ; then 12 class labels
__global__ void k_gather(const float* __restrict__ feat, float* __restrict__ out) {
    int t = blockIdx.x * blockDim.x + threadIdx.x;
    const int NFEAT = NPAIRS * Cc * MAXS;  // 786432
    if (t < NFEAT) {
        int s = t & (MAXS - 1);
        int c = (t >> 10) & (Cc - 1);
        int pair = t >> 16;
        int p = g_idx[pair*MAXS + s];
        int b = pair / 3;
        float val = 0.0f;
        if (p >= 0) val = feat[((size_t)(b*Cc + c)) * Nn + p];
        out[t] = val;
    } else if (t < NFEAT + NPAIRS) {
        int pair = t - NFEAT;
        out[t] = (float)(pair % 3 + 1);
    }
}

extern "C" void kernel_launch(void* const* d_in, const int* in_sizes, int n_in,
                              void* d_out, int out_size) {
    const float* feat   = (const float*)d_in[0];  // [4,64,256,256]
    const int*   labels = (const int*)d_in[1];    // [4,256,256]
    const float* preds  = (const float*)d_in[2];  // [4,4,256,256]
    float* out = (float*)d_out;

    k_argmax<<<(Bb*Nn + 255) / 256, 256>>>(preds);
    k_dilate<<<(Bb*Nn + 255) / 256, 256>>>();
    k_select<<<NPAIRS, 1024>>>(labels);
    int total = NPAIRS*Cc*MAXS + NPAIRS;
    k_gather<<<(total + 255) / 256, 256>>>(feat, out);
}

// round 2
// speedup vs baseline: 4.0170x; 4.0170x over previous
#include <cuda_runtime.h>

#define Bb 4
#define Cc 64
#define Hh 256
#define Ww 256
#define Nn (Hh*Ww)
#define NPAIRS 12
#define HALF_S 512
#define MAXS 1024

__device__ unsigned char g_pred[Bb*Nn];
__device__ unsigned char g_code[Bb*Nn];   // per pixel: lab | (pd<<4)
__device__ int g_idx[NPAIRS*MAXS];

// ---------------- argmax over 4 class planes, 4 pixels/thread ----------------
__global__ void k_argmax(const float* __restrict__ preds) {
    int t = blockIdx.x * blockDim.x + threadIdx.x;   // over B*N/4
    if (t >= Bb*Nn/4) return;
    int b = t / (Nn/4), q = t % (Nn/4);
    const float4* p = (const float4*)(preds + (size_t)b * 4 * Nn) + q;
    float4 v0 = p[0];
    float4 v1 = p[Nn/4];
    float4 v2 = p[2*(Nn/4)];
    float4 v3 = p[3*(Nn/4)];
    unsigned out = 0;
    {
        float a = v0.x; int bi = 0;
        if (v1.x > a) { a = v1.x; bi = 1; }
        if (v2.x > a) { a = v2.x; bi = 2; }
        if (v3.x > a) { a = v3.x; bi = 3; }
        out |= (unsigned)bi;
    }
    {
        float a = v0.y; int bi = 0;
        if (v1.y > a) { a = v1.y; bi = 1; }
        if (v2.y > a) { a = v2.y; bi = 2; }
        if (v3.y > a) { a = v3.y; bi = 3; }
        out |= (unsigned)bi << 8;
    }
    {
        float a = v0.z; int bi = 0;
        if (v1.z > a) { a = v1.z; bi = 1; }
        if (v2.z > a) { a = v2.z; bi = 2; }
        if (v3.z > a) { a = v3.z; bi = 3; }
        out |= (unsigned)bi << 16;
    }
    {
        float a = v0.w; int bi = 0;
        if (v1.w > a) { a = v1.w; bi = 1; }
        if (v2.w > a) { a = v2.w; bi = 2; }
        if (v3.w > a) { a = v3.w; bi = 3; }
        out |= (unsigned)bi << 24;
    }
    ((unsigned*)g_pred)[t] = out;
}

// --------------- 3x3 max-dilate + pack code byte, 4 pixels/thread -----------
__device__ __forceinline__ unsigned rowmax4(const unsigned char* row, int x0) {
    unsigned w = *(const unsigned*)(row + x0);
    unsigned a = (x0 > 0) ? (unsigned)row[x0-1] : 0u;        // class ids >=0 -> 0 is neutral
    unsigned n = (x0 + 4 < Ww) ? (unsigned)row[x0+4] : 0u;
    unsigned wl = (w << 8) | a;
    unsigned wr = (w >> 8) | (n << 24);
    return __vmaxu4(__vmaxu4(w, wl), wr);
}

__global__ void k_dilpack(const int* __restrict__ labels) {
    int t = blockIdx.x * blockDim.x + threadIdx.x;   // over B*N/4
    if (t >= Bb*Nn/4) return;
    int b = t / (Nn/4), q = t % (Nn/4);
    int p = q * 4;
    int y = p >> 8, x0 = p & 255;
    const unsigned char* img = g_pred + b*Nn;
    unsigned m = rowmax4(img + y*Ww, x0);
    if (y > 0)      m = __vmaxu4(m, rowmax4(img + (y-1)*Ww, x0));
    if (y < Hh-1)   m = __vmaxu4(m, rowmax4(img + (y+1)*Ww, x0));
    int4 l = ((const int4*)(labels + b*Nn))[q];
    unsigned lab4 = (unsigned)l.x | ((unsigned)l.y << 8) |
                    ((unsigned)l.z << 16) | ((unsigned)l.w << 24);
    ((unsigned*)g_code)[t] = lab4 | (m << 4);   // each byte value <=3 -> no cross-byte bleed
}

// ---------------- selection: one block per (b,cls) pair ----------------------
// hard rank r -> slot r (r<1024); easy rank e -> slot 512+max(totH-512,0)+e (<1024)
__global__ void k_select() {
    int pair = blockIdx.x;
    int b = pair / 3;
    int cls = pair % 3 + 1;
    int tid = threadIdx.x;
    g_idx[pair*MAXS + tid] = -1;

    const uint4* codes = (const uint4*)(g_code + b*Nn) + tid*4;
    uint4 q0 = codes[0], q1 = codes[1], q2 = codes[2], q3 = codes[3];
    unsigned w[16] = { q0.x,q0.y,q0.z,q0.w, q1.x,q1.y,q1.z,q1.w,
                       q2.x,q2.y,q2.z,q2.w, q3.x,q3.y,q3.z,q3.w };
    const unsigned clsL = (unsigned)cls * 0x01010101u;
    const unsigned clsH = (unsigned)cls * 0x10101010u;

    int hbits = 0, ebits = 0;
#pragma unroll
    for (int i = 0; i < 16; i++) {
        unsigned labm = __vcmpeq4(w[i] & 0x0F0F0F0Fu, clsL);
        unsigned pdm  = __vcmpeq4(w[i] & 0xF0F0F0F0u, clsH);
        ebits += __popc(labm & pdm);
        hbits += __popc(labm & ~pdm);
    }
    int cH = hbits >> 3, cE = ebits >> 3;

    // block-wide inclusive scan of packed (hard<<32 | easy)
    unsigned long long v = ((unsigned long long)cH << 32) | (unsigned)cE;
    unsigned long long own = v;
    int lane = tid & 31, wid = tid >> 5;
#pragma unroll
    for (int o = 1; o < 32; o <<= 1) {
        unsigned long long n = __shfl_up_sync(0xffffffffu, v, o);
        if (lane >= o) v += n;
    }
    __shared__ unsigned long long wsum[32];
    __shared__ unsigned long long s_total;
    if (lane == 31) wsum[wid] = v;
    __syncthreads();
    if (wid == 0) {
        unsigned long long ww = wsum[lane];
#pragma unroll
        for (int o = 1; o < 32; o <<= 1) {
            unsigned long long n = __shfl_up_sync(0xffffffffu, ww, o);
            if (lane >= o) ww += n;
        }
        wsum[lane] = ww;
        if (lane == 31) s_total = ww;
    }
    __syncthreads();

    unsigned long long excl = v - own + (wid > 0 ? wsum[wid-1] : 0ULL);
    int hr = (int)(excl >> 32);
    int er = (int)(excl & 0xffffffffULL);
    int totH = (int)(s_total >> 32);
    int excess = totH > HALF_S ? totH - HALF_S : 0;

    int base = tid * 64;
    int* slots = g_idx + pair*MAXS;
#pragma unroll
    for (int i = 0; i < 16; i++) {
        unsigned labm = __vcmpeq4(w[i] & 0x0F0F0F0Fu, clsL);
        if (!labm) continue;
        unsigned pdm = __vcmpeq4(w[i] & 0xF0F0F0F0u, clsH);
#pragma unroll
        for (int k = 0; k < 4; k++) {
            if ((labm >> (k*8)) & 0xffu) {
                int p = base + i*4 + k;
                if ((pdm >> (k*8)) & 0xffu) {
                    int slot = HALF_S + excess + er;
                    if (slot < MAXS) slots[slot] = p;
                    er++;
                } else {
                    if (hr < MAXS) slots[hr] = p;
                    hr++;
                }
            }
        }
    }
}

// ---------------- gather + labels -------------------------------------------
__global__ void k_gather(const float* __restrict__ feat, float* __restrict__ out) {
    int t = blockIdx.x * blockDim.x + threadIdx.x;
    const int NFEAT = NPAIRS * Cc * MAXS;  // 786432
    if (t < NFEAT) {
        int s = t & (MAXS - 1);
        int c = (t >> 10) & (Cc - 1);
        int pair = t >> 16;
        int p = g_idx[pair*MAXS + s];
        int b = pair / 3;
        float val = 0.0f;
        if (p >= 0) val = __ldg(feat + ((size_t)(b*Cc + c)) * Nn + p);
        out[t] = val;
    } else if (t < NFEAT + NPAIRS) {
        int pair = t - NFEAT;
        out[t] = (float)(pair % 3 + 1);
    }
}

extern "C" void kernel_launch(void* const* d_in, const int* in_sizes, int n_in,
                              void* d_out, int out_size) {
    const float* feat   = (const float*)d_in[0];  // [4,64,256,256]
    const int*   labels = (const int*)d_in[1];    // [4,256,256]
    const float* preds  = (const float*)d_in[2];  // [4,4,256,256]
    float* out = (float*)d_out;

    k_argmax<<<(Bb*Nn/4 + 255) / 256, 256>>>(preds);
    k_dilpack<<<(Bb*Nn/4 + 255) / 256, 256>>>(labels);
    k_select<<<NPAIRS, 1024>>>();
    int total = NPAIRS*Cc*MAXS + NPAIRS;
    k_gather<<<(total + 255) / 256, 256>>>(feat, out);
}

// round 3
// speedup vs baseline: 4.3044x; 1.0715x over previous
#include <cuda_runtime.h>

#define Bb 4
#define Cc 64
#define Hh 256
#define Ww 256
#define Nn (Hh*Ww)
#define NPAIRS 12
#define HALF_S 512
#define MAXS 1024
#define NFEAT (NPAIRS*Cc*MAXS)

#define TILE_R 8          // interior rows per block

__device__ unsigned char g_code[Bb*Nn];   // per pixel: lab | (pd<<4)
__device__ int g_idx[NPAIRS*MAXS];

// ------- fused: argmax over 4 planes -> 3x3 max-dilate -> pack with labels ---
__global__ void k_prep(const float* __restrict__ preds,
                       const int* __restrict__ labels) {
    // grid: Bb * (Hh/TILE_R) blocks, 256 threads (one per column)
    int blk = blockIdx.x;
    int b = blk / (Hh/TILE_R);
    int ty0 = (blk % (Hh/TILE_R)) * TILE_R;     // first interior row
    int tid = threadIdx.x;                       // column 0..255

    __shared__ unsigned char spred[TILE_R+2][Ww];

    const float* pb = preds + (size_t)b * 4 * Nn;
    // compute argmax for rows ty0-1 .. ty0+TILE_R (halo), clamp-out -> 0
#pragma unroll
    for (int r = 0; r < TILE_R+2; r++) {
        int y = ty0 - 1 + r;
        unsigned char cls = 0;
        if (y >= 0 && y < Hh) {
            int off = y*Ww + tid;
            float a = pb[off]; int bi = 0;
            float v1 = pb[Nn   + off];
            float v2 = pb[2*Nn + off];
            float v3 = pb[3*Nn + off];
            if (v1 > a) { a = v1; bi = 1; }
            if (v2 > a) { a = v2; bi = 2; }
            if (v3 > a) { a = v3; bi = 3; }
            cls = (unsigned char)bi;
        }
        spred[r][tid] = cls;
    }
    __syncthreads();

    int xl = tid > 0 ? tid-1 : 0;
    int xr = tid < Ww-1 ? tid+1 : Ww-1;
#pragma unroll
    for (int r = 0; r < TILE_R; r++) {
        int rr = r + 1;  // smem row of interior row ty0+r
        unsigned char m = spred[rr][tid];
        unsigned char v;
        v = spred[rr][xl];   if (v > m) m = v;
        v = spred[rr][xr];   if (v > m) m = v;
        v = spred[rr-1][tid]; if (v > m) m = v;
        v = spred[rr-1][xl];  if (v > m) m = v;
        v = spred[rr-1][xr];  if (v > m) m = v;
        v = spred[rr+1][tid]; if (v > m) m = v;
        v = spred[rr+1][xl];  if (v > m) m = v;
        v = spred[rr+1][xr];  if (v > m) m = v;
        int p = (ty0 + r)*Ww + tid;
        int lab = labels[b*Nn + p];
        g_code[b*Nn + p] = (unsigned char)(lab | (m << 4));
    }
}

// ---------------- selection: one block per (b,cls) pair ----------------------
// hard rank r -> slot r (r<1024); easy rank e -> slot 512+max(totH-512,0)+e (<1024)
__global__ void k_select(float* __restrict__ out) {
    int pair = blockIdx.x;
    int b = pair / 3;
    int cls = pair % 3 + 1;
    int tid = threadIdx.x;
    g_idx[pair*MAXS + tid] = -1;
    if (tid == 0) out[NFEAT + pair] = (float)cls;   // label tail

    const uint4* codes = (const uint4*)(g_code + b*Nn) + tid*4;
    uint4 q0 = codes[0], q1 = codes[1], q2 = codes[2], q3 = codes[3];
    unsigned w[16] = { q0.x,q0.y,q0.z,q0.w, q1.x,q1.y,q1.z,q1.w,
                       q2.x,q2.y,q2.z,q2.w, q3.x,q3.y,q3.z,q3.w };
    const unsigned clsL = (unsigned)cls * 0x01010101u;
    const unsigned clsH = (unsigned)cls * 0x10101010u;

    int hbits = 0, ebits = 0;
#pragma unroll
    for (int i = 0; i < 16; i++) {
        unsigned labm = __vcmpeq4(w[i] & 0x0F0F0F0Fu, clsL);
        unsigned pdm  = __vcmpeq4(w[i] & 0xF0F0F0F0u, clsH);
        ebits += __popc(labm & pdm);
        hbits += __popc(labm & ~pdm);
    }
    int cH = hbits >> 3, cE = ebits >> 3;

    // block-wide inclusive scan of packed (hard<<32 | easy)
    unsigned long long v = ((unsigned long long)cH << 32) | (unsigned)cE;
    unsigned long long own = v;
    int lane = tid & 31, wid = tid >> 5;
#pragma unroll
    for (int o = 1; o < 32; o <<= 1) {
        unsigned long long n = __shfl_up_sync(0xffffffffu, v, o);
        if (lane >= o) v += n;
    }
    __shared__ unsigned long long wsum[32];
    __shared__ unsigned long long s_total;
    if (lane == 31) wsum[wid] = v;
    __syncthreads();
    if (wid == 0) {
        unsigned long long ww = wsum[lane];
#pragma unroll
        for (int o = 1; o < 32; o <<= 1) {
            unsigned long long n = __shfl_up_sync(0xffffffffu, ww, o);
            if (lane >= o) ww += n;
        }
        wsum[lane] = ww;
        if (lane == 31) s_total = ww;
    }
    __syncthreads();

    unsigned long long excl = v - own + (wid > 0 ? wsum[wid-1] : 0ULL);
    int hr = (int)(excl >> 32);
    int er = (int)(excl & 0xffffffffULL);
    int totH = (int)(s_total >> 32);
    int excess = totH > HALF_S ? totH - HALF_S : 0;

    int base = tid * 64;
    int* slots = g_idx + pair*MAXS;
#pragma unroll
    for (int i = 0; i < 16; i++) {
        unsigned labm = __vcmpeq4(w[i] & 0x0F0F0F0Fu, clsL);
        if (!labm) continue;
        unsigned pdm = __vcmpeq4(w[i] & 0xF0F0F0F0u, clsH);
#pragma unroll
        for (int k = 0; k < 4; k++) {
            if ((labm >> (k*8)) & 0xffu) {
                int p = base + i*4 + k;
                if ((pdm >> (k*8)) & 0xffu) {
                    int slot = HALF_S + excess + er;
                    if (slot < MAXS) slots[slot] = p;
                    er++;
                } else {
                    if (hr < MAXS) slots[hr] = p;
                    hr++;
                }
            }
        }
    }
}

// ------------- gather: 4 samples per thread, float4 store -------------------
__global__ void k_gather(const float* __restrict__ feat, float* __restrict__ out) {
    int t = blockIdx.x * blockDim.x + threadIdx.x;   // over NFEAT/4
    if (t >= NFEAT/4) return;
    int s4   = t & 255;              // sample group (4 samples)
    int c    = (t >> 8) & (Cc - 1);
    int pair = t >> 14;
    int b = pair / 3;
    const int* slots = g_idx + pair*MAXS + s4*4;
    const float* plane = feat + ((size_t)(b*Cc + c)) * Nn;
    int p0 = slots[0], p1 = slots[1], p2 = slots[2], p3 = slots[3];
    float4 r;
    r.x = (p0 >= 0) ? __ldg(plane + p0) : 0.0f;
    r.y = (p1 >= 0) ? __ldg(plane + p1) : 0.0f;
    r.z = (p2 >= 0) ? __ldg(plane + p2) : 0.0f;
    r.w = (p3 >= 0) ? __ldg(plane + p3) : 0.0f;
    ((float4*)out)[t] = r;
}

extern "C" void kernel_launch(void* const* d_in, const int* in_sizes, int n_in,
                              void* d_out, int out_size) {
    const float* feat   = (const float*)d_in[0];  // [4,64,256,256]
    const int*   labels = (const int*)d_in[1];    // [4,256,256]
    const float* preds  = (const float*)d_in[2];  // [4,4,256,256]
    float* out = (float*)d_out;

    k_prep<<<Bb*(Hh/TILE_R), 256>>>(preds, labels);
    k_select<<<NPAIRS, 1024>>>(out);
    k_gather<<<(NFEAT/4 + 255) / 256, 256>>>(feat, out);
}